// round 3
// baseline (speedup 1.0000x reference)
#include <cuda_runtime.h>
#include <math.h>

// Problem constants
#define BQ 4
#define SQ 2048
#define DQ 1024
#define MROWS (BQ*SQ)          // 8192
#define NCH 8
#define CH (SQ/NCH)            // 256
#define NCTA 128
#define TPB 256

typedef unsigned long long ull;

// ---------------- scratch (static __device__, no allocations) ----------------
__device__ float g_retained[MROWS*DQ];
__device__ float g_inp[MROWS*DQ];
__device__ float g_gate[MROWS*DQ];
__device__ float g_bm[MROWS*DQ];
__device__ float g_states[MROWS*DQ];
__device__ float g_E[NCH*BQ*DQ];
__device__ float g_Cr[NCH*BQ*DQ];
__device__ float g_blend[2][BQ*DQ];
__device__ unsigned g_flags[NCTA];

__global__ void reset_bar() { g_flags[threadIdx.x] = 0u; }

// packed fp32x2 helpers (Blackwell FFMA2 — only via PTX fma.rn.f32x2)
__device__ __forceinline__ ull ffma2(ull a, ull b, ull c) {
    ull d;
    asm("fma.rn.f32x2 %0, %1, %2, %3;" : "=l"(d) : "l"(a), "l"(b), "l"(c));
    return d;
}
__device__ __forceinline__ ull pack2(float x) {
    ull r;
    asm("mov.b64 %0, {%1, %1};" : "=l"(r) : "f"(x));
    return r;
}
__device__ __forceinline__ void unpack2(ull v, float& lo, float& hi) {
    asm("mov.b64 {%0, %1}, %2;" : "=f"(lo), "=f"(hi) : "l"(v));
}

// ---------------- retention scan (r = dec*r + k*v; retained = q*r) ----------
__global__ __launch_bounds__(TPB) void ret_pass1(const float* __restrict__ K_,
                                                 const float* __restrict__ V_,
                                                 const float* __restrict__ decay) {
    int gid = blockIdx.x * TPB + threadIdx.x;
    int d = gid & (DQ - 1);
    int t2 = gid >> 10;
    int b = t2 & (BQ - 1);
    int c = t2 >> 2;
    float dec = decay[d >> 6];
    long base = ((long)(b * SQ + c * CH)) * DQ + d;
    float E = 0.f;
#pragma unroll 4
    for (int i = 0; i < CH; ++i) {
        E = fmaf(dec, E, K_[base] * V_[base]);
        base += DQ;
    }
    g_E[(c * BQ + b) * DQ + d] = E;
}

__global__ __launch_bounds__(TPB) void ret_pass2(const float* __restrict__ decay) {
    int gid = blockIdx.x * TPB + threadIdx.x;
    int d = gid & (DQ - 1);
    int b = gid >> 10;
    float dec = decay[d >> 6];
    float p = dec;
#pragma unroll
    for (int i = 0; i < 8; ++i) p = p * p;        // dec^256
    float carry = 0.f;
    for (int c = 0; c < NCH; ++c) {
        int idx = (c * BQ + b) * DQ + d;
        g_Cr[idx] = carry;
        carry = fmaf(p, carry, g_E[idx]);
    }
}

__global__ __launch_bounds__(TPB) void ret_pass3(const float* __restrict__ Q_,
                                                 const float* __restrict__ K_,
                                                 const float* __restrict__ V_,
                                                 const float* __restrict__ decay) {
    int gid = blockIdx.x * TPB + threadIdx.x;
    int d = gid & (DQ - 1);
    int t2 = gid >> 10;
    int b = t2 & (BQ - 1);
    int c = t2 >> 2;
    float dec = decay[d >> 6];
    float r = g_Cr[(c * BQ + b) * DQ + d];
    long base = ((long)(b * SQ + c * CH)) * DQ + d;
#pragma unroll 4
    for (int i = 0; i < CH; ++i) {
        r = fmaf(dec, r, K_[base] * V_[base]);
        g_retained[base] = Q_[base] * r;
        base += DQ;
    }
}

// ---------------- big fp32 GEMM: C = X @ W^T + bias (opt sigmoid) -----------
// 128x128 tile, BK=16, 256 thr, 8x8 microtile, FFMA2 packed accumulators.
__global__ __launch_bounds__(256) void gemm_nt(const float* __restrict__ X,
                                               const float* __restrict__ W,
                                               const float* __restrict__ bias,
                                               float* __restrict__ C,
                                               int M, int N, int K, int act) {
    __shared__ float Xs[16][132];
    __shared__ float Ws[16][132];
    const int tid = threadIdx.x;
    const int row0 = blockIdx.y * 128;
    const int col0 = blockIdx.x * 128;
    const int tx = tid & 15, ty = tid >> 4;
    const int lr = tid >> 2, lc = (tid & 3) << 2;
    const float* Xp = X + (long)(row0 + lr) * K + lc;
    const float* Wp = W + (long)(col0 + lr) * K + lc;
    ull accp[4][8];
#pragma unroll
    for (int i = 0; i < 4; ++i)
#pragma unroll
        for (int j = 0; j < 8; ++j) accp[i][j] = 0ull;

    for (int k0 = 0; k0 < K; k0 += 16) {
        float4 xa = *(const float4*)(Xp + k0);
        float4 xb = *(const float4*)(Xp + 64L * K + k0);
        float4 wa = *(const float4*)(Wp + k0);
        float4 wb = *(const float4*)(Wp + 64L * K + k0);
        __syncthreads();
        Xs[lc + 0][lr] = xa.x; Xs[lc + 1][lr] = xa.y; Xs[lc + 2][lr] = xa.z; Xs[lc + 3][lr] = xa.w;
        Xs[lc + 0][lr + 64] = xb.x; Xs[lc + 1][lr + 64] = xb.y; Xs[lc + 2][lr + 64] = xb.z; Xs[lc + 3][lr + 64] = xb.w;
        Ws[lc + 0][lr] = wa.x; Ws[lc + 1][lr] = wa.y; Ws[lc + 2][lr] = wa.z; Ws[lc + 3][lr] = wa.w;
        Ws[lc + 0][lr + 64] = wb.x; Ws[lc + 1][lr + 64] = wb.y; Ws[lc + 2][lr + 64] = wb.z; Ws[lc + 3][lr + 64] = wb.w;
        __syncthreads();
#pragma unroll
        for (int kk = 0; kk < 16; ++kk) {
            const ull* xp2 = reinterpret_cast<const ull*>(&Xs[kk][ty * 8]);
            ull av0 = xp2[0], av1 = xp2[1], av2 = xp2[2], av3 = xp2[3];
            float br[8];
            *(float4*)(br)     = *(const float4*)&Ws[kk][tx * 8];
            *(float4*)(br + 4) = *(const float4*)&Ws[kk][tx * 8 + 4];
            ull bb[8];
#pragma unroll
            for (int jj = 0; jj < 8; ++jj) bb[jj] = pack2(br[jj]);
#pragma unroll
            for (int jj = 0; jj < 8; ++jj) {
                accp[0][jj] = ffma2(av0, bb[jj], accp[0][jj]);
                accp[1][jj] = ffma2(av1, bb[jj], accp[1][jj]);
                accp[2][jj] = ffma2(av2, bb[jj], accp[2][jj]);
                accp[3][jj] = ffma2(av3, bb[jj], accp[3][jj]);
            }
        }
    }
    float bj[8];
#pragma unroll
    for (int jj = 0; jj < 8; ++jj) bj[jj] = bias ? bias[col0 + tx * 8 + jj] : 0.f;
#pragma unroll
    for (int ip = 0; ip < 4; ++ip) {
        float olo[8], ohi[8];
#pragma unroll
        for (int jj = 0; jj < 8; ++jj) {
            float l, h;
            unpack2(accp[ip][jj], l, h);
            l += bj[jj]; h += bj[jj];
            if (act) { l = 1.f / (1.f + expf(-l)); h = 1.f / (1.f + expf(-h)); }
            olo[jj] = l; ohi[jj] = h;
        }
        long rl = row0 + ty * 8 + 2 * ip;
        *(float4*)&C[rl * N + col0 + tx * 8]     = make_float4(olo[0], olo[1], olo[2], olo[3]);
        *(float4*)&C[rl * N + col0 + tx * 8 + 4] = make_float4(olo[4], olo[5], olo[6], olo[7]);
        long rh = rl + 1;
        *(float4*)&C[rh * N + col0 + tx * 8]     = make_float4(ohi[0], ohi[1], ohi[2], ohi[3]);
        *(float4*)&C[rh * N + col0 + tx * 8 + 4] = make_float4(ohi[4], ohi[5], ohi[6], ohi[7]);
    }
}

// ---------------- persistent sequential scan (the A GEMM recurrence) --------
// 128 CTAs, each owns 8 columns of A (SMEM-resident). Flag-array sync per step:
// each CTA stores its own flag word (no atomic serialization); every CTA's
// warp 0 polls all 128 flags directly (no central hop).
#define SCAN_SMEM ((8*1028 + 4*1028 + 256) * 4)

__global__ __launch_bounds__(TPB, 1) void scan_kernel(const float* __restrict__ A) {
    extern __shared__ float sm[];
    float* As = sm;                         // 8 rows x 1028 (padded)
    float* bl = sm + 8 * 1028;              // 4 rows x 1028
    float* part = sm + 8 * 1028 + 4 * 1028; // 8 warps x 32
    const int tid = threadIdx.x, w = tid >> 5, lane = tid & 31;
    const int c0 = blockIdx.x * 8;

    // load A slice once
    for (int i = tid; i < 8 * DQ; i += TPB) {
        int j = i >> 10, kk = i & 1023;
        As[j * 1028 + kk] = A[(long)(c0 + j) * DQ + kk];
    }

    const int j = lane >> 2, b = lane & 3;  // warp0 lane -> (col, batch)
    const int colg = c0 + j;
    float st = 0.f, gv = 0.f, iv = 0.f, mv = 0.f, gv_n = 0.f, iv_n = 0.f, mv_n = 0.f;
    if (w == 0) {
        long off = (long)(b * SQ) * DQ + colg;
        gv = g_gate[off]; iv = g_inp[off]; mv = g_bm[off];
    }
    __syncthreads();

    for (int t = 0; t < SQ; ++t) {
        const int p = t & 1;
        if (w == 0) {
            // blended = gate*state + (1-gate)*inp = inp + gate*(state-inp)
            float blv = fmaf(gv, st - iv, iv);
            g_blend[p][b * DQ + colg] = blv;
            __syncwarp();
            if (lane == 0) {
                __threadfence();
                asm volatile("st.relaxed.gpu.u32 [%0], %1;"
                             :: "l"(&g_flags[blockIdx.x]), "r"((unsigned)(t + 1)) : "memory");
            }
            // prefetch next step's gate/inp/bm (overlaps the poll)
            if (t + 1 < SQ) {
                long off = ((long)b * SQ + (t + 1)) * DQ + colg;
                gv_n = g_gate[off]; iv_n = g_inp[off]; mv_n = g_bm[off];
            }
            // poll all 128 flags (4 per lane)
            const unsigned tgt = (unsigned)(t + 1);
            bool ok;
            do {
                unsigned a0, a1, a2, a3;
                asm volatile("ld.acquire.gpu.u32 %0, [%1];" : "=r"(a0) : "l"(g_flags + lane));
                asm volatile("ld.acquire.gpu.u32 %0, [%1];" : "=r"(a1) : "l"(g_flags + lane + 32));
                asm volatile("ld.acquire.gpu.u32 %0, [%1];" : "=r"(a2) : "l"(g_flags + lane + 64));
                asm volatile("ld.acquire.gpu.u32 %0, [%1];" : "=r"(a3) : "l"(g_flags + lane + 96));
                unsigned m = min(min(a0, a1), min(a2, a3));
                ok = __all_sync(0xffffffffu, m >= tgt);
            } while (!ok);
        }
        __syncthreads();
        // gather full blended vector into SMEM
        const float* gb = g_blend[p];
        for (int i4 = tid; i4 < BQ * DQ / 4; i4 += TPB) {
            float4 x = ((const float4*)gb)[i4];
            int bb = i4 >> 8, kk = (i4 & 255) << 2;
            *(float4*)(bl + bb * 1028 + kk) = x;
        }
        __syncthreads();
        // K-split GEMV: warp w covers k in [128w, 128w+128), lane owns (j,b)
        ull acc0 = 0ull, acc1 = 0ull;
        const float* Aj = As + j * 1028 + w * 128;
        const float* Bb = bl + b * 1028 + w * 128;
#pragma unroll
        for (int kk = 0; kk < 128; kk += 4) {
            const ull* ap = reinterpret_cast<const ull*>(Aj + kk);
            const ull* bp = reinterpret_cast<const ull*>(Bb + kk);
            acc0 = ffma2(ap[0], bp[0], acc0);
            acc1 = ffma2(ap[1], bp[1], acc1);
        }
        float l0, h0, l1, h1;
        unpack2(acc0, l0, h0);
        unpack2(acc1, l1, h1);
        part[w * 32 + lane] = (l0 + h0) + (l1 + h1);
        __syncthreads();
        if (w == 0) {
            float ssum = 0.f;
#pragma unroll
            for (int q8 = 0; q8 < 8; ++q8) ssum += part[q8 * 32 + lane];
            st = tanhf(ssum + mv);
            g_states[((long)b * SQ + t) * DQ + colg] = st;
            gv = gv_n; iv = iv_n; mv = mv_n;
        }
    }
}

// ---------------- launch ----------------------------------------------------
extern "C" void kernel_launch(void* const* d_in, const int* in_sizes, int n_in,
                              void* d_out, int out_size) {
    const float* q     = (const float*)d_in[0];
    const float* k     = (const float*)d_in[1];
    const float* v     = (const float*)d_in[2];
    const float* Wi    = (const float*)d_in[3];
    const float* bi    = (const float*)d_in[4];
    const float* Wg    = (const float*)d_in[5];
    const float* bg    = (const float*)d_in[6];
    const float* A     = (const float*)d_in[7];
    const float* Bm    = (const float*)d_in[8];
    const float* Wo    = (const float*)d_in[9];
    const float* bo    = (const float*)d_in[10];
    const float* decay = (const float*)d_in[11];
    float* out = (float*)d_out;

    float *retained, *inp, *gate, *bm, *states;
    cudaGetSymbolAddress((void**)&retained, g_retained);
    cudaGetSymbolAddress((void**)&inp, g_inp);
    cudaGetSymbolAddress((void**)&gate, g_gate);
    cudaGetSymbolAddress((void**)&bm, g_bm);
    cudaGetSymbolAddress((void**)&states, g_states);

    cudaFuncSetAttribute(scan_kernel, cudaFuncAttributeMaxDynamicSharedMemorySize, SCAN_SMEM);

    // 1) retention prefix scan -> retained
    ret_pass1<<<(NCH * BQ * DQ) / TPB, TPB>>>(k, v, decay);
    ret_pass2<<<(BQ * DQ) / TPB, TPB>>>(decay);
    ret_pass3<<<(NCH * BQ * DQ) / TPB, TPB>>>(q, k, v, decay);

    // 2) parallel big GEMMs
    dim3 gg(DQ / 128, MROWS / 128);
    gemm_nt<<<gg, 256>>>(retained, Wi, bi, inp, MROWS, DQ, DQ, 0);
    gemm_nt<<<gg, 256>>>(inp, Wg, bg, gate, MROWS, DQ, DQ, 1);
    gemm_nt<<<gg, 256>>>(inp, Bm, (const float*)nullptr, bm, MROWS, DQ, DQ, 0);

    // 3) sequential state recurrence (persistent, flag-array sync per step)
    reset_bar<<<1, NCTA>>>();
    scan_kernel<<<NCTA, TPB, SCAN_SMEM>>>(A);

    // 4) output projection
    gemm_nt<<<gg, 256>>>(states, Wo, bo, out, MROWS, DQ, DQ, 0);
}

// round 4
// speedup vs baseline: 1.4111x; 1.4111x over previous
#include <cuda_runtime.h>
#include <math.h>

// Problem constants
#define BQ 4
#define SQ 2048
#define DQ 1024
#define MROWS (BQ*SQ)          // 8192
#define NCH 8
#define CH (SQ/NCH)            // 256
#define NCTA 128
#define TPB 256

// ---------------- scratch (static __device__, no allocations) ----------------
__device__ float g_retained[MROWS*DQ];
__device__ float g_inp[MROWS*DQ];
__device__ float g_gate[MROWS*DQ];
__device__ float g_bm[MROWS*DQ];
__device__ float g_states[MROWS*DQ];
__device__ float g_E[NCH*BQ*DQ];
__device__ float g_Cr[NCH*BQ*DQ];
// blend exchange buffer, permuted layout: [parity][cta*32 + b*8 + j]
__device__ float g_blend[2][NCTA*32];
__device__ unsigned g_ctr;

__global__ void reset_bar() { g_ctr = 0u; }

// ---------------- retention scan (r = dec*r + k*v; retained = q*r) ----------
__global__ __launch_bounds__(TPB) void ret_pass1(const float* __restrict__ K_,
                                                 const float* __restrict__ V_,
                                                 const float* __restrict__ decay) {
    int gid = blockIdx.x * TPB + threadIdx.x;
    int d = gid & (DQ - 1);
    int t2 = gid >> 10;
    int b = t2 & (BQ - 1);
    int c = t2 >> 2;
    float dec = decay[d >> 6];
    long base = ((long)(b * SQ + c * CH)) * DQ + d;
    float E = 0.f;
#pragma unroll 4
    for (int i = 0; i < CH; ++i) {
        E = fmaf(dec, E, K_[base] * V_[base]);
        base += DQ;
    }
    g_E[(c * BQ + b) * DQ + d] = E;
}

__global__ __launch_bounds__(TPB) void ret_pass2(const float* __restrict__ decay) {
    int gid = blockIdx.x * TPB + threadIdx.x;
    int d = gid & (DQ - 1);
    int b = gid >> 10;
    float dec = decay[d >> 6];
    float p = dec;
#pragma unroll
    for (int i = 0; i < 8; ++i) p = p * p;        // dec^256
    float carry = 0.f;
    for (int c = 0; c < NCH; ++c) {
        int idx = (c * BQ + b) * DQ + d;
        g_Cr[idx] = carry;
        carry = fmaf(p, carry, g_E[idx]);
    }
}

__global__ __launch_bounds__(TPB) void ret_pass3(const float* __restrict__ Q_,
                                                 const float* __restrict__ K_,
                                                 const float* __restrict__ V_,
                                                 const float* __restrict__ decay) {
    int gid = blockIdx.x * TPB + threadIdx.x;
    int d = gid & (DQ - 1);
    int t2 = gid >> 10;
    int b = t2 & (BQ - 1);
    int c = t2 >> 2;
    float dec = decay[d >> 6];
    float r = g_Cr[(c * BQ + b) * DQ + d];
    long base = ((long)(b * SQ + c * CH)) * DQ + d;
#pragma unroll 4
    for (int i = 0; i < CH; ++i) {
        r = fmaf(dec, r, K_[base] * V_[base]);
        g_retained[base] = Q_[base] * r;
        base += DQ;
    }
}

// ---------------- big fp32 GEMM: C = X @ W^T + bias (opt sigmoid) -----------
// X:[M,K] row-major, W:[N,K] row-major. 128x128 tile, BK=16, 256 thr, 8x8/thr.
__global__ __launch_bounds__(256) void gemm_nt(const float* __restrict__ X,
                                               const float* __restrict__ W,
                                               const float* __restrict__ bias,
                                               float* __restrict__ C,
                                               int M, int N, int K, int act) {
    __shared__ float Xs[16][132];
    __shared__ float Ws[16][132];
    const int tid = threadIdx.x;
    const int row0 = blockIdx.y * 128;
    const int col0 = blockIdx.x * 128;
    const int tx = tid & 15, ty = tid >> 4;
    const int lr = tid >> 2, lc = (tid & 3) << 2;
    const float* Xp = X + (long)(row0 + lr) * K + lc;
    const float* Wp = W + (long)(col0 + lr) * K + lc;
    float acc[8][8] = {};
    for (int k0 = 0; k0 < K; k0 += 16) {
        float4 xa = *(const float4*)(Xp + k0);
        float4 xb = *(const float4*)(Xp + 64L * K + k0);
        float4 wa = *(const float4*)(Wp + k0);
        float4 wb = *(const float4*)(Wp + 64L * K + k0);
        __syncthreads();
        Xs[lc + 0][lr] = xa.x; Xs[lc + 1][lr] = xa.y; Xs[lc + 2][lr] = xa.z; Xs[lc + 3][lr] = xa.w;
        Xs[lc + 0][lr + 64] = xb.x; Xs[lc + 1][lr + 64] = xb.y; Xs[lc + 2][lr + 64] = xb.z; Xs[lc + 3][lr + 64] = xb.w;
        Ws[lc + 0][lr] = wa.x; Ws[lc + 1][lr] = wa.y; Ws[lc + 2][lr] = wa.z; Ws[lc + 3][lr] = wa.w;
        Ws[lc + 0][lr + 64] = wb.x; Ws[lc + 1][lr + 64] = wb.y; Ws[lc + 2][lr + 64] = wb.z; Ws[lc + 3][lr + 64] = wb.w;
        __syncthreads();
#pragma unroll
        for (int kk = 0; kk < 16; ++kk) {
            float a[8], br[8];
            *(float4*)(a)     = *(const float4*)&Xs[kk][ty * 8];
            *(float4*)(a + 4) = *(const float4*)&Xs[kk][ty * 8 + 4];
            *(float4*)(br)     = *(const float4*)&Ws[kk][tx * 8];
            *(float4*)(br + 4) = *(const float4*)&Ws[kk][tx * 8 + 4];
#pragma unroll
            for (int i = 0; i < 8; ++i)
#pragma unroll
                for (int jj = 0; jj < 8; ++jj)
                    acc[i][jj] = fmaf(a[i], br[jj], acc[i][jj]);
        }
    }
    float bj[8];
#pragma unroll
    for (int jj = 0; jj < 8; ++jj) bj[jj] = bias ? bias[col0 + tx * 8 + jj] : 0.f;
#pragma unroll
    for (int i = 0; i < 8; ++i) {
        long row = row0 + ty * 8 + i;
        float o[8];
#pragma unroll
        for (int jj = 0; jj < 8; ++jj) {
            float v = acc[i][jj] + bj[jj];
            if (act) v = 1.f / (1.f + expf(-v));
            o[jj] = v;
        }
        *(float4*)&C[row * N + col0 + tx * 8]     = make_float4(o[0], o[1], o[2], o[3]);
        *(float4*)&C[row * N + col0 + tx * 8 + 4] = make_float4(o[4], o[5], o[6], o[7]);
    }
}

// ---------------- persistent sequential scan (the A GEMM recurrence) --------
// 128 CTAs, each owns 8 columns of A (SMEM-resident).
// Barrier: single monotonic counter; each CTA does one red.release.gpu.add;
// only tid0 polls (ld.relaxed loop + one ld.acquire). Blend exchange is one
// coalesced 128B line per CTA, layout [cta][b][j].
#define SCAN_SMEM ((8*1028 + 4*1028 + 256) * 4)

__global__ __launch_bounds__(TPB, 1) void scan_kernel(const float* __restrict__ A) {
    extern __shared__ float sm[];
    float* As = sm;                         // 8 rows x 1028 (padded)
    float* bl = sm + 8 * 1028;              // 4 rows x 1028
    float* part = sm + 8 * 1028 + 4 * 1028; // 8 warps x 32
    const int tid = threadIdx.x, w = tid >> 5, lane = tid & 31;
    const int c0 = blockIdx.x * 8;

    // load A slice once
    for (int i = tid; i < 8 * DQ; i += TPB) {
        int j = i >> 10, kk = i & 1023;
        As[j * 1028 + kk] = A[(long)(c0 + j) * DQ + kk];
    }

    const int j = lane >> 2, b = lane & 3;  // single lane mapping everywhere
    const int colg = c0 + j;
    // slot within this CTA's 128B blend line: b*8 + j
    const int slot = b * 8 + j;
    float st = 0.f, gv = 0.f, iv = 0.f, mv = 0.f, gv_n = 0.f, iv_n = 0.f, mv_n = 0.f;
    if (w == 0) {
        long off = (long)(b * SQ) * DQ + colg;
        gv = g_gate[off]; iv = g_inp[off]; mv = g_bm[off];
        if (SQ > 1) {
            long off1 = ((long)b * SQ + 1) * DQ + colg;
            gv_n = g_gate[off1]; iv_n = g_inp[off1]; mv_n = g_bm[off1];
        }
    }
    __syncthreads();

    // preamble: blend for t=0 (st = 0)
    if (w == 0) {
        float blv = fmaf(gv, st - iv, iv);
        g_blend[0][blockIdx.x * 32 + slot] = blv;
    }

    unsigned target = 0;
    for (int t = 0; t < SQ; ++t) {
        __syncthreads();  // orders this CTA's blend-t stores before the release
        target += NCTA;
        if (tid == 0) {
            unsigned c;
            asm volatile("red.release.gpu.global.add.u32 [%0], %1;"
                         :: "l"(&g_ctr), "r"(1u) : "memory");
            do {
                asm volatile("ld.relaxed.gpu.u32 %0, [%1];" : "=r"(c) : "l"(&g_ctr) : "memory");
            } while (c < target);
            asm volatile("ld.acquire.gpu.u32 %0, [%1];" : "=r"(c) : "l"(&g_ctr) : "memory");
        }
        __syncthreads();  // publish acquire to whole CTA

        // stage blended vector into SMEM (un-permute [cta][b][j] -> bl[b][col])
        const int p = t & 1;
        const float* gb = g_blend[p];
        for (int i4 = tid; i4 < NCTA * 32 / 4; i4 += TPB) {
            float4 x = ((const float4*)gb)[i4];
            int idx = i4 << 2;
            int cta = idx >> 5, bb = (idx >> 3) & 3, jj = idx & 7;
            *(float4*)(bl + bb * 1028 + cta * 8 + jj) = x;
        }
        __syncthreads();

        // K-split GEMV: warp w covers k in [128w, 128w+128), lane owns (j,b)
        float a0 = 0.f, a1 = 0.f, a2 = 0.f, a3 = 0.f;
        const float* Aj = As + j * 1028 + w * 128;
        const float* Bb = bl + b * 1028 + w * 128;
#pragma unroll
        for (int kk = 0; kk < 128; kk += 4) {
            float4 av = *(const float4*)(Aj + kk);
            float4 bv = *(const float4*)(Bb + kk);
            a0 = fmaf(av.x, bv.x, a0);
            a1 = fmaf(av.y, bv.y, a1);
            a2 = fmaf(av.z, bv.z, a2);
            a3 = fmaf(av.w, bv.w, a3);
        }
        part[w * 32 + lane] = (a0 + a1) + (a2 + a3);
        __syncthreads();

        if (w == 0) {
            float ssum = 0.f;
#pragma unroll
            for (int q8 = 0; q8 < 8; ++q8) ssum += part[q8 * 32 + lane];
            st = tanhf(ssum + mv);
            g_states[((long)b * SQ + t) * DQ + colg] = st;
            gv = gv_n; iv = iv_n; mv = mv_n;
            if (t + 1 < SQ) {
                float blv = fmaf(gv, st - iv, iv);
                g_blend[(t + 1) & 1][blockIdx.x * 32 + slot] = blv;
                if (t + 2 < SQ) {
                    long off = ((long)b * SQ + (t + 2)) * DQ + colg;
                    gv_n = g_gate[off]; iv_n = g_inp[off]; mv_n = g_bm[off];
                }
            }
        }
    }
}

// ---------------- launch ----------------------------------------------------
extern "C" void kernel_launch(void* const* d_in, const int* in_sizes, int n_in,
                              void* d_out, int out_size) {
    const float* q     = (const float*)d_in[0];
    const float* k     = (const float*)d_in[1];
    const float* v     = (const float*)d_in[2];
    const float* Wi    = (const float*)d_in[3];
    const float* bi    = (const float*)d_in[4];
    const float* Wg    = (const float*)d_in[5];
    const float* bg    = (const float*)d_in[6];
    const float* A     = (const float*)d_in[7];
    const float* Bm    = (const float*)d_in[8];
    const float* Wo    = (const float*)d_in[9];
    const float* bo    = (const float*)d_in[10];
    const float* decay = (const float*)d_in[11];
    float* out = (float*)d_out;

    float *retained, *inp, *gate, *bm, *states;
    cudaGetSymbolAddress((void**)&retained, g_retained);
    cudaGetSymbolAddress((void**)&inp, g_inp);
    cudaGetSymbolAddress((void**)&gate, g_gate);
    cudaGetSymbolAddress((void**)&bm, g_bm);
    cudaGetSymbolAddress((void**)&states, g_states);

    cudaFuncSetAttribute(scan_kernel, cudaFuncAttributeMaxDynamicSharedMemorySize, SCAN_SMEM);

    // 1) retention prefix scan -> retained
    ret_pass1<<<(NCH * BQ * DQ) / TPB, TPB>>>(k, v, decay);
    ret_pass2<<<(BQ * DQ) / TPB, TPB>>>(decay);
    ret_pass3<<<(NCH * BQ * DQ) / TPB, TPB>>>(q, k, v, decay);

    // 2) parallel big GEMMs
    dim3 gg(DQ / 128, MROWS / 128);
    gemm_nt<<<gg, 256>>>(retained, Wi, bi, inp, MROWS, DQ, DQ, 0);
    gemm_nt<<<gg, 256>>>(inp, Wg, bg, gate, MROWS, DQ, DQ, 1);
    gemm_nt<<<gg, 256>>>(inp, Bm, (const float*)nullptr, bm, MROWS, DQ, DQ, 0);

    // 3) sequential state recurrence (persistent, monotonic-counter barrier)
    reset_bar<<<1, 1>>>();
    scan_kernel<<<NCTA, TPB, SCAN_SMEM>>>(A);

    // 4) output projection
    gemm_nt<<<gg, 256>>>(states, Wo, bo, out, MROWS, DQ, DQ, 0);
}

// round 8
// speedup vs baseline: 1.8172x; 1.2877x over previous
#include <cuda_runtime.h>
#include <math.h>

// Problem constants
#define BQ 4
#define SQ 2048
#define DQ 1024
#define MROWS (BQ*SQ)          // 8192
#define NCH 8
#define CH (SQ/NCH)            // 256
#define NCTA 128
#define TPB 256

typedef unsigned long long ull;

// ---------------- scratch (static __device__, no allocations) ----------------
__device__ float g_retained[MROWS*DQ];
__device__ float g_inp[MROWS*DQ];
__device__ float g_gate[MROWS*DQ];
__device__ float g_bm[MROWS*DQ];
__device__ float g_states[MROWS*DQ];
__device__ float g_E[NCH*BQ*DQ];
__device__ float g_Cr[NCH*BQ*DQ];
// mailbox: per-source payload (32 floats = 128B line), double buffered, + tag
__device__ float g_pay[2][NCTA][32];
__device__ unsigned g_tag[NCTA][32];   // one 128B line per source, word 0 used

__global__ void reset_bar() { g_tag[blockIdx.x][threadIdx.x] = 0u; }

// packed fp32x2 helpers (Blackwell FFMA2 via PTX)
__device__ __forceinline__ ull ffma2(ull a, ull b, ull c) {
    ull d;
    asm("fma.rn.f32x2 %0, %1, %2, %3;" : "=l"(d) : "l"(a), "l"(b), "l"(c));
    return d;
}
__device__ __forceinline__ void unpack2(ull v, float& lo, float& hi) {
    asm("mov.b64 {%0, %1}, %2;" : "=f"(lo), "=f"(hi) : "l"(v));
}

// ---------------- retention scan (r = dec*r + k*v; retained = q*r) ----------
__global__ __launch_bounds__(TPB) void ret_pass1(const float* __restrict__ K_,
                                                 const float* __restrict__ V_,
                                                 const float* __restrict__ decay) {
    int gid = blockIdx.x * TPB + threadIdx.x;
    int d = gid & (DQ - 1);
    int t2 = gid >> 10;
    int b = t2 & (BQ - 1);
    int c = t2 >> 2;
    float dec = decay[d >> 6];
    long base = ((long)(b * SQ + c * CH)) * DQ + d;
    float E = 0.f;
#pragma unroll 4
    for (int i = 0; i < CH; ++i) {
        E = fmaf(dec, E, K_[base] * V_[base]);
        base += DQ;
    }
    g_E[(c * BQ + b) * DQ + d] = E;
}

__global__ __launch_bounds__(TPB) void ret_pass2(const float* __restrict__ decay) {
    int gid = blockIdx.x * TPB + threadIdx.x;
    int d = gid & (DQ - 1);
    int b = gid >> 10;
    float dec = decay[d >> 6];
    float p = dec;
#pragma unroll
    for (int i = 0; i < 8; ++i) p = p * p;        // dec^256
    float carry = 0.f;
    for (int c = 0; c < NCH; ++c) {
        int idx = (c * BQ + b) * DQ + d;
        g_Cr[idx] = carry;
        carry = fmaf(p, carry, g_E[idx]);
    }
}

__global__ __launch_bounds__(TPB) void ret_pass3(const float* __restrict__ Q_,
                                                 const float* __restrict__ K_,
                                                 const float* __restrict__ V_,
                                                 const float* __restrict__ decay) {
    int gid = blockIdx.x * TPB + threadIdx.x;
    int d = gid & (DQ - 1);
    int t2 = gid >> 10;
    int b = t2 & (BQ - 1);
    int c = t2 >> 2;
    float dec = decay[d >> 6];
    float r = g_Cr[(c * BQ + b) * DQ + d];
    long base = ((long)(b * SQ + c * CH)) * DQ + d;
#pragma unroll 4
    for (int i = 0; i < CH; ++i) {
        r = fmaf(dec, r, K_[base] * V_[base]);
        g_retained[base] = Q_[base] * r;
        base += DQ;
    }
}

// ---------------- big fp32 GEMM: C = X @ W^T + bias (opt sigmoid) -----------
__global__ __launch_bounds__(256) void gemm_nt(const float* __restrict__ X,
                                               const float* __restrict__ W,
                                               const float* __restrict__ bias,
                                               float* __restrict__ C,
                                               int M, int N, int K, int act) {
    __shared__ float Xs[16][132];
    __shared__ float Ws[16][132];
    const int tid = threadIdx.x;
    const int row0 = blockIdx.y * 128;
    const int col0 = blockIdx.x * 128;
    const int tx = tid & 15, ty = tid >> 4;
    const int lr = tid >> 2, lc = (tid & 3) << 2;
    const float* Xp = X + (long)(row0 + lr) * K + lc;
    const float* Wp = W + (long)(col0 + lr) * K + lc;
    float acc[8][8] = {};
    for (int k0 = 0; k0 < K; k0 += 16) {
        float4 xa = *(const float4*)(Xp + k0);
        float4 xb = *(const float4*)(Xp + 64L * K + k0);
        float4 wa = *(const float4*)(Wp + k0);
        float4 wb = *(const float4*)(Wp + 64L * K + k0);
        __syncthreads();
        Xs[lc + 0][lr] = xa.x; Xs[lc + 1][lr] = xa.y; Xs[lc + 2][lr] = xa.z; Xs[lc + 3][lr] = xa.w;
        Xs[lc + 0][lr + 64] = xb.x; Xs[lc + 1][lr + 64] = xb.y; Xs[lc + 2][lr + 64] = xb.z; Xs[lc + 3][lr + 64] = xb.w;
        Ws[lc + 0][lr] = wa.x; Ws[lc + 1][lr] = wa.y; Ws[lc + 2][lr] = wa.z; Ws[lc + 3][lr] = wa.w;
        Ws[lc + 0][lr + 64] = wb.x; Ws[lc + 1][lr + 64] = wb.y; Ws[lc + 2][lr + 64] = wb.z; Ws[lc + 3][lr + 64] = wb.w;
        __syncthreads();
#pragma unroll
        for (int kk = 0; kk < 16; ++kk) {
            float a[8], br[8];
            *(float4*)(a)     = *(const float4*)&Xs[kk][ty * 8];
            *(float4*)(a + 4) = *(const float4*)&Xs[kk][ty * 8 + 4];
            *(float4*)(br)     = *(const float4*)&Ws[kk][tx * 8];
            *(float4*)(br + 4) = *(const float4*)&Ws[kk][tx * 8 + 4];
#pragma unroll
            for (int i = 0; i < 8; ++i)
#pragma unroll
                for (int jj = 0; jj < 8; ++jj)
                    acc[i][jj] = fmaf(a[i], br[jj], acc[i][jj]);
        }
    }
    float bj[8];
#pragma unroll
    for (int jj = 0; jj < 8; ++jj) bj[jj] = bias ? bias[col0 + tx * 8 + jj] : 0.f;
#pragma unroll
    for (int i = 0; i < 8; ++i) {
        long row = row0 + ty * 8 + i;
        float o[8];
#pragma unroll
        for (int jj = 0; jj < 8; ++jj) {
            float v = acc[i][jj] + bj[jj];
            if (act) v = 1.f / (1.f + expf(-v));
            o[jj] = v;
        }
        *(float4*)&C[row * N + col0 + tx * 8]     = make_float4(o[0], o[1], o[2], o[3]);
        *(float4*)&C[row * N + col0 + tx * 8 + 4] = make_float4(o[4], o[5], o[6], o[7]);
    }
}

// ---------------- persistent sequential scan (the A GEMM recurrence) --------
// Decentralized mailbox sync (see R5), now with the A slice held in REGISTERS:
// warp w covers k in [128w,128w+128); lane (j=l>>2, q=l&3) permanently holds
// A[c0+j][128w+16i+4q], i=0..7 (32 regs). Per step each lane computes 4
// batch-partial dot products over its 32 k values (bl via broadcast LDS.128,
// 4q-interleave -> conflict-free), then a 2-round shfl.xor butterfly over the
// q bits yields the (j, b=l&3) output per lane. One __syncthreads per step.
__global__ __launch_bounds__(TPB, 1) void scan_kernel(const float* __restrict__ A) {
    __shared__ float bl[4 * 1028];          // blended, 4 batches x 1028 (padded)
    __shared__ float part[2][256];          // parity-split warp partials
    const int tid = threadIdx.x, w = tid >> 5, lane = tid & 31;
    const int cta = blockIdx.x;
    const int c0 = cta * 8;
    const int j = lane >> 2, q = lane & 3, b = lane & 3;
    const int colg = c0 + j;
    const int slot = b * 8 + j;             // position in payload line

    // A slice -> registers (once)
    ull a2[16];
    {
        const float* Arow = A + (long)(c0 + j) * DQ + 128 * w + 4 * q;
#pragma unroll
        for (int i = 0; i < 8; ++i) {
            float4 t = *(const float4*)(Arow + 16 * i);
            a2[2 * i]     = ((const ull*)&t)[0];
            a2[2 * i + 1] = ((const ull*)&t)[1];
        }
    }

    float st = 0.f, gv = 0.f, iv = 0.f, mv = 0.f, gv_n = 0.f, iv_n = 0.f, mv_n = 0.f;
    unsigned* mytag = &g_tag[cta][0];
    if (w == 0) {
        long off = (long)(b * SQ) * DQ + colg;
        gv = g_gate[off]; iv = g_inp[off]; mv = g_bm[off];
        if (SQ > 1) {
            long off1 = ((long)b * SQ + 1) * DQ + colg;
            gv_n = g_gate[off1]; iv_n = g_inp[off1]; mv_n = g_bm[off1];
        }
        // preamble: publish blend_0 (st = 0), tag := 1
        float blv = fmaf(gv, st - iv, iv);
        g_pay[0][cta][slot] = blv;
        __syncwarp();
        if (lane == 0)
            asm volatile("st.release.gpu.u32 [%0], %1;" :: "l"(mytag), "r"(1u) : "memory");
    }
    __syncthreads();

    const unsigned* wtag = &g_tag[16 * w + (lane & 15)][0];

    for (int t = 0; t < SQ; ++t) {
        const int p = t & 1;
        const unsigned tgt = (unsigned)(t + 1);
        // ---- poll this warp's 16 source tags (acquire) ----
        bool ok;
        do {
            unsigned v = tgt;
            if (lane < 16)
                asm volatile("ld.acquire.gpu.u32 %0, [%1];" : "=r"(v) : "l"(wtag) : "memory");
            ok = __all_sync(0xffffffffu, v >= tgt);
        } while (!ok);

        // ---- fetch 2KB payload for this warp's 16 sources, stage into bl ----
#pragma unroll
        for (int i = 0; i < 4; ++i) {
            int idx = lane * 4 + i;
            int s_local = idx >> 3, bb = (idx >> 1) & 3, half = idx & 1;
            float4 x = *(const float4*)&g_pay[p][16 * w + s_local][bb * 8 + half * 4];
            *(float4*)(bl + bb * 1028 + (16 * w + s_local) * 8 + half * 4) = x;
        }
        __syncwarp();

        // ---- GEMV: A from regs, bl from SMEM (broadcast, conflict-free) ----
        float accb[4];
        const float* blw = bl + 128 * w + 4 * q;
#pragma unroll
        for (int b2 = 0; b2 < 4; ++b2) {
            ull acc0 = 0ull, acc1 = 0ull;
            const float* bp = blw + b2 * 1028;
#pragma unroll
            for (int i = 0; i < 8; ++i) {
                const ull* bp2 = (const ull*)(bp + 16 * i);
                acc0 = ffma2(a2[2 * i],     bp2[0], acc0);
                acc1 = ffma2(a2[2 * i + 1], bp2[1], acc1);
            }
            float l0, h0, l1, h1;
            unpack2(acc0, l0, h0);
            unpack2(acc1, l1, h1);
            accb[b2] = (l0 + h0) + (l1 + h1);
        }
        // butterfly over q bits: lane ends with the sum for batch b = q
        {
            float s0 = (q & 1) ? accb[0] : accb[1];
            float s2 = (q & 1) ? accb[2] : accb[3];
            float t0 = __shfl_xor_sync(0xffffffffu, s0, 1);
            float t2 = __shfl_xor_sync(0xffffffffu, s2, 1);
            float u0 = ((q & 1) ? accb[1] : accb[0]) + t0;  // b = q&1
            float u2 = ((q & 1) ? accb[3] : accb[2]) + t2;  // b = (q&1)+2
            float s  = (q & 2) ? u0 : u2;
            float r  = __shfl_xor_sync(0xffffffffu, s, 2);
            part[p][w * 32 + lane] = ((q & 2) ? u2 : u0) + r;
        }
        __syncthreads();

        // ---- reduce + tanh + publish next blend (warp0 only) ----
        if (w == 0) {
            float ssum = 0.f;
#pragma unroll
            for (int q8 = 0; q8 < 8; ++q8) ssum += part[p][q8 * 32 + lane];
            st = tanhf(ssum + mv);
            gv = gv_n; iv = iv_n; mv = mv_n;
            if (t + 1 < SQ) {
                float blv = fmaf(gv, st - iv, iv);
                g_pay[(t + 1) & 1][cta][slot] = blv;
                __syncwarp();
                if (lane == 0)
                    asm volatile("st.release.gpu.u32 [%0], %1;"
                                 :: "l"(mytag), "r"((unsigned)(t + 2)) : "memory");
            }
            g_states[((long)b * SQ + t) * DQ + colg] = st;
            if (t + 2 < SQ) {
                long off = ((long)b * SQ + (t + 2)) * DQ + colg;
                gv_n = g_gate[off]; iv_n = g_inp[off]; mv_n = g_bm[off];
            }
        }
    }
}

// ---------------- launch ----------------------------------------------------
extern "C" void kernel_launch(void* const* d_in, const int* in_sizes, int n_in,
                              void* d_out, int out_size) {
    const float* q     = (const float*)d_in[0];
    const float* k     = (const float*)d_in[1];
    const float* v     = (const float*)d_in[2];
    const float* Wi    = (const float*)d_in[3];
    const float* bi    = (const float*)d_in[4];
    const float* Wg    = (const float*)d_in[5];
    const float* bg    = (const float*)d_in[6];
    const float* A     = (const float*)d_in[7];
    const float* Bm    = (const float*)d_in[8];
    const float* Wo    = (const float*)d_in[9];
    const float* bo    = (const float*)d_in[10];
    const float* decay = (const float*)d_in[11];
    float* out = (float*)d_out;

    float *retained, *inp, *gate, *bm, *states;
    cudaGetSymbolAddress((void**)&retained, g_retained);
    cudaGetSymbolAddress((void**)&inp, g_inp);
    cudaGetSymbolAddress((void**)&gate, g_gate);
    cudaGetSymbolAddress((void**)&bm, g_bm);
    cudaGetSymbolAddress((void**)&states, g_states);

    // 1) retention prefix scan -> retained
    ret_pass1<<<(NCH * BQ * DQ) / TPB, TPB>>>(k, v, decay);
    ret_pass2<<<(BQ * DQ) / TPB, TPB>>>(decay);
    ret_pass3<<<(NCH * BQ * DQ) / TPB, TPB>>>(q, k, v, decay);

    // 2) parallel big GEMMs
    dim3 gg(DQ / 128, MROWS / 128);
    gemm_nt<<<gg, 256>>>(retained, Wi, bi, inp, MROWS, DQ, DQ, 0);
    gemm_nt<<<gg, 256>>>(inp, Wg, bg, gate, MROWS, DQ, DQ, 1);
    gemm_nt<<<gg, 256>>>(inp, Bm, (const float*)nullptr, bm, MROWS, DQ, DQ, 0);

    // 3) sequential state recurrence (decentralized mailbox sync, reg-A GEMV)
    reset_bar<<<NCTA, 32>>>();
    scan_kernel<<<NCTA, TPB>>>(A);

    // 4) output projection
    gemm_nt<<<gg, 256>>>(states, Wo, bo, out, MROWS, DQ, DQ, 0);
}